// round 15
// baseline (speedup 1.0000x reference)
#include <cuda_runtime.h>
#include <cuda_bf16.h>
#include <cuda_fp16.h>

#define NN 50000
#define EE 1000000
#define BB 512
#define HH 128
#define MID 64
#define IN1 54
#define IN2 18

typedef unsigned long long u64;
typedef unsigned int u32;

#define FMA2(d, a, b, c) asm("fma.rn.f32x2 %0, %1, %2, %3;" : "=l"(d) : "l"(a), "l"(b), "l"(c))

__device__ __forceinline__ u64 pack2(float lo, float hi) {
    u64 r; asm("mov.b64 %0, {%1, %2};" : "=l"(r) : "f"(lo), "f"(hi)); return r;
}
__device__ __forceinline__ void unpack2(u64 v, float& lo, float& hi) {
    asm("mov.b64 {%0, %1}, %2;" : "=f"(lo), "=f"(hi) : "l"(v));
}
__device__ __forceinline__ void red_add_v4(float* addr, float4 v) {
    asm volatile("red.global.add.v4.f32 [%0], {%1, %2, %3, %4};"
                 :: "l"(addr), "f"(v.x), "f"(v.y), "f"(v.z), "f"(v.w) : "memory");
}
__device__ __forceinline__ void red_add_v2(float* addr, float a, float b) {
    asm volatile("red.global.add.v2.f32 [%0], {%1, %2};"
                 :: "l"(addr), "f"(a), "f"(b) : "memory");
}
__device__ __forceinline__ void red_add_f(float* addr, float v) {
    asm volatile("red.global.add.f32 [%0], %1;" :: "l"(addr), "f"(v) : "memory");
}
// bf16 mma (node chain)
#define MMA16816(c0, c1, c2, c3, a0, a1, a2, a3, b0, b1) \
    asm volatile("mma.sync.aligned.m16n8k16.row.col.f32.bf16.bf16.f32 " \
                 "{%0,%1,%2,%3}, {%4,%5,%6,%7}, {%8,%9}, {%0,%1,%2,%3};" \
                 : "+f"(c0), "+f"(c1), "+f"(c2), "+f"(c3) \
                 : "r"(a0), "r"(a1), "r"(a2), "r"(a3), "r"(b0), "r"(b1))
// fp16 mma (edge path)
#define MMAH16816(c0, c1, c2, c3, a0, a1, a2, a3, b0, b1) \
    asm volatile("mma.sync.aligned.m16n8k16.row.col.f32.f16.f16.f32 " \
                 "{%0,%1,%2,%3}, {%4,%5,%6,%7}, {%8,%9}, {%0,%1,%2,%3};" \
                 : "+f"(c0), "+f"(c1), "+f"(c2), "+f"(c3) \
                 : "r"(a0), "r"(a1), "r"(a2), "r"(a3), "r"(b0), "r"(b1))

__device__ __forceinline__ u32 pack_bf2(float e0, float e1) {
    __nv_bfloat162 h = __floats2bfloat162_rn(e0, e1);
    return *(u32*)&h;
}
__device__ __forceinline__ u32 pack_h2(float e0, float e1) {
    __half2 h = __floats2half2_rn(e0, e1);
    return *(u32*)&h;
}

// ---------------- scratch ----------------
__device__ float g_xact[NN * HH];
__device__ float g_agg1[NN * HH];
__device__ float g_agg2[NN * HH];
__device__ float g_A[NN * HH];
__device__ float g_B[NN * HH];
__device__ float g_C[NN * HH];
__device__ float g_D[NN * HH];
__device__ float g_mean[BB * HH];
__device__ float g_var[BB * HH];
__device__ float g_cnt[BB];
__device__ __half g_m1h[EE * MID];   // single fp16 per element
__device__ __half g_m2h[EE * MID];
// preconverted node-GEMM weights: 13 matrices of 128x128, bf16 hi/lo planes (flat [c][k])
__device__ __nv_bfloat16 g_Wh[13 * 128 * 128];
__device__ __nv_bfloat16 g_Wl[13 * 128 * 128];

__global__ void zero_kernel() {
    int idx = blockIdx.x * blockDim.x + threadIdx.x;
    if (idx < NN * HH) { g_agg1[idx] = 0.f; g_agg2[idx] = 0.f; }
    if (idx < BB * HH) { g_mean[idx] = 0.f; g_var[idx] = 0.f; }
    if (idx < BB) g_cnt[idx] = 0.f;
}

// ---------------- weight prep: fp32 -> bf16 hi/lo planes ----------------
struct WSrc { const float* p; int ldw; };
struct WPack { WSrc w[13]; };

__global__ void prep_weights(WPack wp) {
    int idx = blockIdx.x * blockDim.x + threadIdx.x;
    if (idx >= 13 * 16384) return;
    int m = idx >> 14, r = idx & 16383, c = r >> 7, k = r & 127;
    float v = wp.w[m].p[(size_t)c * wp.w[m].ldw + k];
    __nv_bfloat16 h = __float2bfloat16_rn(v);
    g_Wh[idx] = h;
    g_Wl[idx] = __float2bfloat16_rn(v - __bfloat162float(h));
}

// ---------------- persistent node GEMM via split-bf16 HMMA ----------------
constexpr int GP = 136;
constexpr int GEMM_SMEM = (64 + 64 + 128 + 128) * GP * 2;

template <bool ACCUM, bool EPI, bool SWISH, bool RESID, int FUSE>
__global__ __launch_bounds__(256, 2) void gemm_p(
    const float* __restrict__ A, int widx,
    const float* __restrict__ bias, const float* __restrict__ resid,
    float* __restrict__ out, int nrows,
    const int* __restrict__ batch, const float* __restrict__ nw, const float* __restrict__ nb)
{
    extern __shared__ char smc[];
    __nv_bfloat16* Ahi = (__nv_bfloat16*)(smc);
    __nv_bfloat16* Alo = (__nv_bfloat16*)(smc + 64 * GP * 2);
    __nv_bfloat16* Whi = (__nv_bfloat16*)(smc + 128 * GP * 2);
    __nv_bfloat16* Wlo = (__nv_bfloat16*)(smc + 256 * GP * 2);

    const int tid  = threadIdx.x;
    const int warp = tid >> 5;
    const int lane = tid & 31;
    const int fg   = lane >> 2;
    const int ft   = lane & 3;
    const int rg   = warp & 3;
    const int chf  = warp >> 2;

    {
        const u32* srcH = (const u32*)(g_Wh + (size_t)widx * 16384);
        const u32* srcL = (const u32*)(g_Wl + (size_t)widx * 16384);
        for (int i = tid; i < 128 * 64; i += 256) {
            int c = i >> 6, kp = i & 63;
            ((u32*)Whi)[c * 68 + kp] = srcH[i];
            ((u32*)Wlo)[c * 68 + kp] = srcL[i];
        }
    }

    const int ntiles = (nrows + 63) >> 6;

    float4 pre[8];
    auto ldA = [&](int tt) {
#pragma unroll
        for (int j = 0; j < 8; j++) {
            int idx = tid + 256 * j;
            int r = idx >> 5, kp4 = idx & 31;
            int gr = (tt << 6) + r;
            float4 v = (gr < nrows) ? *(const float4*)(A + (size_t)gr * 128 + 4 * kp4)
                                    : make_float4(0.f, 0.f, 0.f, 0.f);
            if (FUSE == 2) {
                if (gr < nrows) {
                    int b = __ldg(batch + gr);
                    float rcnt = 1.f / fmaxf(g_cnt[b], 1.f);
                    float4 vv = *(const float4*)(&g_var[b * HH + 4 * kp4]);
                    float4 w4 = *(const float4*)(nw + 4 * kp4);
                    float4 b4 = *(const float4*)(nb + 4 * kp4);
                    v.x = w4.x * v.x * rsqrtf(vv.x * rcnt + 1e-5f) + b4.x;
                    v.y = w4.y * v.y * rsqrtf(vv.y * rcnt + 1e-5f) + b4.y;
                    v.z = w4.z * v.z * rsqrtf(vv.z * rcnt + 1e-5f) + b4.z;
                    v.w = w4.w * v.w * rsqrtf(vv.w * rcnt + 1e-5f) + b4.w;
                }
            }
            pre[j] = v;
        }
    };

    int t = blockIdx.x;
    if (t < ntiles) ldA(t);

    for (; t < ntiles; t += gridDim.x) {
        const int r0 = t << 6;
        __syncthreads();

#pragma unroll
        for (int j = 0; j < 8; j++) {
            int idx = tid + 256 * j;
            int r = idx >> 5, kp4 = idx & 31;
            float4 v = pre[j];
            __nv_bfloat162 h01 = __floats2bfloat162_rn(v.x, v.y);
            __nv_bfloat162 h23 = __floats2bfloat162_rn(v.z, v.w);
            __nv_bfloat162 l01 = __floats2bfloat162_rn(v.x - __bfloat162float(h01.x),
                                                       v.y - __bfloat162float(h01.y));
            __nv_bfloat162 l23 = __floats2bfloat162_rn(v.z - __bfloat162float(h23.x),
                                                       v.w - __bfloat162float(h23.y));
            ((u64*)(Ahi + r * GP))[kp4] = (u64)(*(u32*)&h01) | ((u64)(*(u32*)&h23) << 32);
            ((u64*)(Alo + r * GP))[kp4] = (u64)(*(u32*)&l01) | ((u64)(*(u32*)&l23) << 32);
        }
        __syncthreads();

        const int tn = t + gridDim.x;
        if (tn < ntiles) ldA(tn);

        float acc[8][4];
#pragma unroll
        for (int nt = 0; nt < 8; nt++)
#pragma unroll
            for (int q = 0; q < 4; q++) acc[nt][q] = 0.f;

        const int m0 = rg * 16 + fg;
#pragma unroll
        for (int kstep = 0; kstep < 8; kstep++) {
            const int k0 = kstep * 16 + 2 * ft;
            u32 ah0 = *(const u32*)(Ahi + m0 * GP + k0);
            u32 ah1 = *(const u32*)(Ahi + (m0 + 8) * GP + k0);
            u32 ah2 = *(const u32*)(Ahi + m0 * GP + k0 + 8);
            u32 ah3 = *(const u32*)(Ahi + (m0 + 8) * GP + k0 + 8);
            u32 al0 = *(const u32*)(Alo + m0 * GP + k0);
            u32 al1 = *(const u32*)(Alo + (m0 + 8) * GP + k0);
            u32 al2 = *(const u32*)(Alo + m0 * GP + k0 + 8);
            u32 al3 = *(const u32*)(Alo + (m0 + 8) * GP + k0 + 8);
#pragma unroll
            for (int nt = 0; nt < 8; nt++) {
                const int c = chf * 64 + nt * 8 + fg;
                u32 bh0 = *(const u32*)(Whi + c * GP + k0);
                u32 bh1 = *(const u32*)(Whi + c * GP + k0 + 8);
                u32 bl0 = *(const u32*)(Wlo + c * GP + k0);
                u32 bl1 = *(const u32*)(Wlo + c * GP + k0 + 8);
                MMA16816(acc[nt][0], acc[nt][1], acc[nt][2], acc[nt][3],
                         ah0, ah1, ah2, ah3, bh0, bh1);
                MMA16816(acc[nt][0], acc[nt][1], acc[nt][2], acc[nt][3],
                         al0, al1, al2, al3, bh0, bh1);
                MMA16816(acc[nt][0], acc[nt][1], acc[nt][2], acc[nt][3],
                         ah0, ah1, ah2, ah3, bl0, bl1);
            }
        }

        const int rA = r0 + m0, rBr = r0 + m0 + 8;
        int bA = 0, bB = 0;
        if (FUSE == 1) {
            if (rA < nrows)  bA = __ldg(batch + rA);
            if (rBr < nrows) bB = __ldg(batch + rBr);
        }
#pragma unroll
        for (int nt = 0; nt < 8; nt++) {
            const int c = chf * 64 + nt * 8 + 2 * ft;
            float v0 = acc[nt][0], v1 = acc[nt][1];
            float v2 = acc[nt][2], v3 = acc[nt][3];
            if (EPI) {
                float2 bv = *(const float2*)(bias + c);
                v0 += bv.x; v1 += bv.y; v2 += bv.x; v3 += bv.y;
            }
            if (rA < nrows) {
                float* orow = out + (size_t)rA * 128 + c;
                if (ACCUM) { float2 pv = *(const float2*)orow; v0 += pv.x; v1 += pv.y; }
                if (SWISH) {
                    v0 = v0 / (1.f + __expf(-v0));
                    v1 = v1 / (1.f + __expf(-v1));
                }
                if (RESID) {
                    float2 rv = *(const float2*)(resid + (size_t)rA * 128 + c);
                    v0 += rv.x; v1 += rv.y;
                }
                *(float2*)orow = make_float2(v0, v1);
                if (FUSE == 1) red_add_v2(&g_mean[bA * HH + c], v0, v1);
            }
            if (rBr < nrows) {
                float* orow = out + (size_t)rBr * 128 + c;
                if (ACCUM) { float2 pv = *(const float2*)orow; v2 += pv.x; v3 += pv.y; }
                if (SWISH) {
                    v2 = v2 / (1.f + __expf(-v2));
                    v3 = v3 / (1.f + __expf(-v3));
                }
                if (RESID) {
                    float2 rv = *(const float2*)(resid + (size_t)rBr * 128 + c);
                    v2 += rv.x; v3 += rv.y;
                }
                *(float2*)orow = make_float2(v2, v3);
                if (FUSE == 1) red_add_v2(&g_mean[bB * HH + c], v2, v3);
            }
        }
        if (FUSE == 1 && chf == 0 && ft == 0) {
            if (rA < nrows)  red_add_f(&g_cnt[bA], 1.f);
            if (rBr < nrows) red_add_f(&g_cnt[bB], 1.f);
        }
    }
}

// ---------------- edge stage 1: m stored as single fp16 ----------------
constexpr int EB = 16;

__global__ __launch_bounds__(256) void edge_mlp1(
    const float* __restrict__ feat1, const float* __restrict__ feat2,
    const float* __restrict__ W1a, const float* __restrict__ W1b, int nE)
{
    __shared__ __align__(16) float f1s[EB * IN1];
    __shared__ __align__(16) float f2s[EB * IN2];
    __shared__ __align__(16) float Ws1a[MID * IN1];
    __shared__ __align__(16) float Ws1b[MID * IN2];

    const int tid = threadIdx.x;
    for (int i = tid; i < MID * IN1; i += 256) Ws1a[i] = W1a[i];
    for (int i = tid; i < MID * IN2; i += 256) Ws1b[i] = W1b[i];
    __syncthreads();

    const int ntiles = nE / EB;
    const int k = tid & 63, g = tid >> 6;

    for (int t = blockIdx.x; t < ntiles; t += gridDim.x) {
        const int e0 = t * EB;
        for (int i = tid; i < EB * IN1; i += 256) f1s[i] = feat1[(size_t)e0 * IN1 + i];
        for (int i = tid; i < EB * IN2; i += 256) f2s[i] = feat2[(size_t)e0 * IN2 + i];
        __syncthreads();

        {
            const u64* wrow = (const u64*)(Ws1a + k * IN1);
            const u64* fr0 = (const u64*)(f1s + (g + 0)  * IN1);
            const u64* fr1 = (const u64*)(f1s + (g + 4)  * IN1);
            const u64* fr2 = (const u64*)(f1s + (g + 8)  * IN1);
            const u64* fr3 = (const u64*)(f1s + (g + 12) * IN1);
            u64 a0 = 0ull, a1 = 0ull, a2 = 0ull, a3 = 0ull;
#pragma unroll
            for (int jp = 0; jp < IN1 / 2; jp++) {
                u64 w = wrow[jp];
                FMA2(a0, fr0[jp], w, a0);
                FMA2(a1, fr1[jp], w, a1);
                FMA2(a2, fr2[jp], w, a2);
                FMA2(a3, fr3[jp], w, a3);
            }
            float lo, hi;
#pragma unroll
            for (int q = 0; q < 4; q++) {
                u64 a = (q == 0) ? a0 : (q == 1) ? a1 : (q == 2) ? a2 : a3;
                unpack2(a, lo, hi);
                g_m1h[(size_t)(e0 + g + 4 * q) * MID + k] = __float2half_rn(lo + hi);
            }
        }
        {
            const u64* wrow = (const u64*)(Ws1b + k * IN2);
            const u64* fr0 = (const u64*)(f2s + (g + 0)  * IN2);
            const u64* fr1 = (const u64*)(f2s + (g + 4)  * IN2);
            const u64* fr2 = (const u64*)(f2s + (g + 8)  * IN2);
            const u64* fr3 = (const u64*)(f2s + (g + 12) * IN2);
            u64 a0 = 0ull, a1 = 0ull, a2 = 0ull, a3 = 0ull;
#pragma unroll
            for (int jp = 0; jp < IN2 / 2; jp++) {
                u64 w = wrow[jp];
                FMA2(a0, fr0[jp], w, a0);
                FMA2(a1, fr1[jp], w, a1);
                FMA2(a2, fr2[jp], w, a2);
                FMA2(a3, fr3[jp], w, a3);
            }
            float lo, hi;
#pragma unroll
            for (int q = 0; q < 4; q++) {
                u64 a = (q == 0) ? a0 : (q == 1) ? a1 : (q == 2) ? a2 : a3;
                unpack2(a, lo, hi);
                g_m2h[(size_t)(e0 + g + 4 * q) * MID + k] = __float2half_rn(lo + hi);
            }
        }
        __syncthreads();
    }
}

// ---------------- edge stage 2: fp16 1-term HMMA ----------------
constexpr int XP = 132;
constexpr int EB2 = 32;

__global__ __launch_bounds__(256, 3) void edge_scatter(
    const int* __restrict__ ei,
    const float* __restrict__ W2a, const float* __restrict__ W2b,
    const float* __restrict__ xact,
    float* __restrict__ agg1, float* __restrict__ agg2, int nE)
{
    __shared__ __align__(16) float xs[2][EB2 * XP];

    const int tid  = threadIdx.x;
    const int warp = tid >> 5;
    const int lane = tid & 31;
    const int fg   = lane >> 2;
    const int ft   = lane & 3;

    u32 bhf[4][4][2];
    {
        const float* W2 = (warp < 4) ? W2a : W2b;
        const int nbase = (warp & 3) * 32;
#pragma unroll
        for (int nt = 0; nt < 4; nt++) {
            const float* wrow = W2 + (size_t)(nbase + nt * 8 + fg) * MID;
#pragma unroll
            for (int kt = 0; kt < 4; kt++) {
#pragma unroll
                for (int half = 0; half < 2; half++) {
                    int k0 = kt * 16 + half * 8 + 2 * ft;
                    bhf[nt][kt][half] = pack_h2(wrow[k0], wrow[k0 + 1]);
                }
            }
        }
    }

    const int ntiles = nE / EB2;

    auto do_gather = [&](int buf, int tt) {
        const int e0n = tt * EB2;
#pragma unroll
        for (int j = 0; j < 4; j++) {
            int idx = tid + 256 * j;
            int e = idx >> 5, h4 = (idx & 31) << 2;
            int src = __ldg(ei + e0n + e);
            float4 v = *(const float4*)(xact + (size_t)src * HH + h4);
            *(float4*)(&xs[buf][e * XP + h4]) = v;
        }
    };

    int t = blockIdx.x;
    if (t < ntiles) do_gather(0, t);

    int it = 0;
    for (; t < ntiles; t += gridDim.x, it ^= 1) {
        const int cur = it, nxt = it ^ 1;
        const int tn = t + gridDim.x;
        __syncthreads();
        if (tn < ntiles) do_gather(nxt, tn);

        const __half* mpl = (warp < 4) ? g_m1h : g_m2h;
        float* agg = (warp < 4) ? agg1 : agg2;
        const int nbase = (warp & 3) * 32;

#pragma unroll
        for (int sb = 0; sb < 2; sb++) {
            const int e0 = t * EB2 + sb * 16;
            const int exs = sb * 16;

            float acc[4][4];
#pragma unroll
            for (int nt = 0; nt < 4; nt++)
#pragma unroll
                for (int q = 0; q < 4; q++) acc[nt][q] = 0.f;

            const u32* rowA = (const u32*)(mpl + (size_t)(e0 + fg) * MID);
            const u32* rowB = (const u32*)(mpl + (size_t)(e0 + fg + 8) * MID);
#pragma unroll
            for (int kt = 0; kt < 4; kt++) {
                u32 a0 = rowA[kt * 8 + ft];
                u32 a1 = rowB[kt * 8 + ft];
                u32 a2 = rowA[kt * 8 + ft + 4];
                u32 a3 = rowB[kt * 8 + ft + 4];
#pragma unroll
                for (int nt = 0; nt < 4; nt++) {
                    MMAH16816(acc[nt][0], acc[nt][1], acc[nt][2], acc[nt][3],
                              a0, a1, a2, a3, bhf[nt][kt][0], bhf[nt][kt][1]);
                }
            }

            const int dA = __ldg(ei + nE + e0 + fg);
            const int dB = __ldg(ei + nE + e0 + fg + 8);
#pragma unroll
            for (int nt = 0; nt < 4; nt++) {
                int ch = nbase + nt * 8 + 2 * ft;
                float2 xga = *(const float2*)(&xs[cur][(exs + fg) * XP + ch]);
                float2 xgb = *(const float2*)(&xs[cur][(exs + fg + 8) * XP + ch]);
                red_add_v2(agg + (size_t)dA * HH + ch, acc[nt][0] * xga.x, acc[nt][1] * xga.y);
                red_add_v2(agg + (size_t)dB * HH + ch, acc[nt][2] * xgb.x, acc[nt][3] * xgb.y);
            }
        }
    }
}

// ---------------- GraphNorm center ----------------
__global__ void norm_center(const float* __restrict__ hin, const int* __restrict__ batch,
                            const float* __restrict__ ms, float* __restrict__ hc_out) {
    int idx = blockIdx.x * blockDim.x + threadIdx.x;
    if (idx >= NN * 32) return;
    int n = idx >> 5, c4 = (idx & 31) << 2;
    int b = batch[n];
    float rcnt = 1.f / fmaxf(g_cnt[b], 1.f);
    float4 hv = *(const float4*)(hin + (size_t)n * HH + c4);
    float4 mv = *(const float4*)(&g_mean[b * HH + c4]);
    float4 msv = *(const float4*)(ms + c4);
    float4 hc;
    hc.x = hv.x - mv.x * rcnt * msv.x;
    hc.y = hv.y - mv.y * rcnt * msv.y;
    hc.z = hv.z - mv.z * rcnt * msv.z;
    hc.w = hv.w - mv.w * rcnt * msv.w;
    *(float4*)(hc_out + (size_t)n * HH + c4) = hc;
    float4 sq = make_float4(hc.x * hc.x, hc.y * hc.y, hc.z * hc.z, hc.w * hc.w);
    red_add_v4(&g_var[b * HH + c4], sq);
}

// ---------------- launch ----------------
extern "C" void kernel_launch(void* const* d_in, const int* in_sizes, int n_in,
                              void* d_out, int out_size)
{
    const float* x        = (const float*)d_in[0];
    const float* feature1 = (const float*)d_in[1];
    const float* feature2 = (const float*)d_in[2];
    const int*   ei       = (const int*)d_in[3];
    const int*   batch    = (const int*)d_in[4];
    const float* lin_W    = (const float*)d_in[5];
    const float* lin_b    = (const float*)d_in[6];
    const float* f1_W1    = (const float*)d_in[7];
    const float* f1_W2    = (const float*)d_in[8];
    const float* f2_W1    = (const float*)d_in[9];
    const float* f2_W2    = (const float*)d_in[10];
    const float* c1_rel_W = (const float*)d_in[11];
    const float* c1_rel_b = (const float*)d_in[12];
    const float* c1_rt_W  = (const float*)d_in[13];
    const float* c2_rel_W = (const float*)d_in[14];
    const float* c2_rel_b = (const float*)d_in[15];
    const float* c2_rt_W  = (const float*)d_in[16];
    const float* lin1_W   = (const float*)d_in[17];
    const float* lin1_b   = (const float*)d_in[18];
    const float* lin2_W   = (const float*)d_in[19];
    const float* lin2_b   = (const float*)d_in[20];
    const float* cat_W    = (const float*)d_in[21];
    const float* cat_b    = (const float*)d_in[22];
    const float* norm_w   = (const float*)d_in[23];
    const float* norm_b   = (const float*)d_in[24];
    const float* norm_ms  = (const float*)d_in[25];
    const float* lins_W   = (const float*)d_in[26];
    const float* lins_b   = (const float*)d_in[27];
    const float* final_W  = (const float*)d_in[28];
    const float* final_b  = (const float*)d_in[29];

    const int nN = in_sizes[0] / HH;
    const int nE = in_sizes[3] / 2;

    float *pxact, *pagg1, *pagg2, *pA, *pB, *pC, *pD;
    cudaGetSymbolAddress((void**)&pxact, g_xact);
    cudaGetSymbolAddress((void**)&pagg1, g_agg1);
    cudaGetSymbolAddress((void**)&pagg2, g_agg2);
    cudaGetSymbolAddress((void**)&pA, g_A);
    cudaGetSymbolAddress((void**)&pB, g_B);
    cudaGetSymbolAddress((void**)&pC, g_C);
    cudaGetSymbolAddress((void**)&pD, g_D);

    cudaFuncSetAttribute(gemm_p<false, true,  true,  false, 0>, cudaFuncAttributeMaxDynamicSharedMemorySize, GEMM_SMEM);
    cudaFuncSetAttribute(gemm_p<false, false, false, false, 0>, cudaFuncAttributeMaxDynamicSharedMemorySize, GEMM_SMEM);
    cudaFuncSetAttribute(gemm_p<true,  true,  false, false, 0>, cudaFuncAttributeMaxDynamicSharedMemorySize, GEMM_SMEM);
    cudaFuncSetAttribute(gemm_p<true,  true,  false, true,  0>, cudaFuncAttributeMaxDynamicSharedMemorySize, GEMM_SMEM);
    cudaFuncSetAttribute(gemm_p<false, true,  true,  true,  0>, cudaFuncAttributeMaxDynamicSharedMemorySize, GEMM_SMEM);
    cudaFuncSetAttribute(gemm_p<false, true,  true,  true,  1>, cudaFuncAttributeMaxDynamicSharedMemorySize, GEMM_SMEM);
    cudaFuncSetAttribute(gemm_p<false, true,  false, false, 2>, cudaFuncAttributeMaxDynamicSharedMemorySize, GEMM_SMEM);

    const int PG = 296;

    // side streams + events for captured fork-join (infra handles; created once,
    // captured graph identical every call)
    static cudaStream_t s1 = nullptr, s2 = nullptr;
    static cudaEvent_t evRoot = nullptr, evP = nullptr, evM = nullptr,
                       evS = nullptr, evB2 = nullptr;
    if (s1 == nullptr) {
        cudaStreamCreateWithFlags(&s1, cudaStreamNonBlocking);
        cudaStreamCreateWithFlags(&s2, cudaStreamNonBlocking);
        cudaEventCreateWithFlags(&evRoot, cudaEventDisableTiming);
        cudaEventCreateWithFlags(&evP, cudaEventDisableTiming);
        cudaEventCreateWithFlags(&evM, cudaEventDisableTiming);
        cudaEventCreateWithFlags(&evS, cudaEventDisableTiming);
        cudaEventCreateWithFlags(&evB2, cudaEventDisableTiming);
    }

    WPack wp;
    wp.w[0]  = { lin_W, HH };
    wp.w[1]  = { c1_rel_W, HH };
    wp.w[2]  = { c1_rt_W, HH };
    wp.w[3]  = { lin1_W, HH };
    wp.w[4]  = { c2_rel_W, HH };
    wp.w[5]  = { c2_rt_W, HH };
    wp.w[6]  = { lin2_W, HH };
    wp.w[7]  = { cat_W, 2 * HH };
    wp.w[8]  = { cat_W + HH, 2 * HH };
    wp.w[9]  = { lins_W + 0 * HH * HH, HH };
    wp.w[10] = { lins_W + 1 * HH * HH, HH };
    wp.w[11] = { lins_W + 2 * HH * HH, HH };
    wp.w[12] = { final_W, HH };

    // ---- fork: s1 = prep_weights, s2 = edge_mlp1, main = zero ----
    cudaEventRecord(evRoot, 0);
    cudaStreamWaitEvent(s1, evRoot, 0);
    cudaStreamWaitEvent(s2, evRoot, 0);

    prep_weights<<<(13 * 16384 + 255) / 256, 256, 0, s1>>>(wp);
    cudaEventRecord(evP, s1);

    edge_mlp1<<<592, 256, 0, s2>>>(feature1, feature2, f1_W1, f2_W1, nE);
    cudaEventRecord(evM, s2);

    zero_kernel<<<(NN * HH + 255) / 256, 256>>>();

    // main: x_act gemm (needs prep)
    cudaStreamWaitEvent(0, evP, 0);
    gemm_p<false, true, true, false, 0><<<PG, 256, GEMM_SMEM>>>(
        x, 0, lin_b, nullptr, pxact, nN, nullptr, nullptr, nullptr);

    // main: scatter (needs mlp1 + xact + zero)
    cudaStreamWaitEvent(0, evM, 0);
    edge_scatter<<<444, 256>>>(ei, f1_W2, f2_W2, pxact, pagg1, pagg2, nE);
    cudaEventRecord(evS, 0);

    // ---- branch 2 on s1: t2/h2 path -> pD, pC ----
    cudaStreamWaitEvent(s1, evS, 0);
    gemm_p<false, false, false, false, 0><<<PG, 256, GEMM_SMEM, s1>>>(
        pagg2, 4, nullptr, nullptr, pD, nN, nullptr, nullptr, nullptr);
    gemm_p<true, true, false, false, 0><<<PG, 256, GEMM_SMEM, s1>>>(
        pxact, 5, c2_rel_b, nullptr, pD, nN, nullptr, nullptr, nullptr);
    gemm_p<false, true, true, false, 0><<<PG, 256, GEMM_SMEM, s1>>>(
        pD, 6, lin2_b, nullptr, pC, nN, nullptr, nullptr, nullptr);
    cudaEventRecord(evB2, s1);

    // ---- branch 1 on main: t1/h1 path -> pA, pB; then h1@cat1 -> pA ----
    gemm_p<false, false, false, false, 0><<<PG, 256, GEMM_SMEM>>>(
        pagg1, 1, nullptr, nullptr, pA, nN, nullptr, nullptr, nullptr);
    gemm_p<true, true, false, false, 0><<<PG, 256, GEMM_SMEM>>>(
        pxact, 2, c1_rel_b, nullptr, pA, nN, nullptr, nullptr, nullptr);
    gemm_p<false, true, true, false, 0><<<PG, 256, GEMM_SMEM>>>(
        pA, 3, lin1_b, nullptr, pB, nN, nullptr, nullptr, nullptr);
    gemm_p<false, false, false, false, 0><<<PG, 256, GEMM_SMEM>>>(
        pB, 7, nullptr, nullptr, pA, nN, nullptr, nullptr, nullptr);

    // join: h2@cat2 accum (needs branch 2's pC)
    cudaStreamWaitEvent(0, evB2, 0);
    gemm_p<true, true, false, true, 0><<<PG, 256, GEMM_SMEM>>>(
        pC, 8, cat_b, pxact, pA, nN, nullptr, nullptr, nullptr);

    // residual swish layers; last fuses GraphNorm mean/cnt
    gemm_p<false, true, true, true, 0><<<PG, 256, GEMM_SMEM>>>(
        pA, 9,  lins_b + 0 * HH, pA, pB, nN, nullptr, nullptr, nullptr);
    gemm_p<false, true, true, true, 0><<<PG, 256, GEMM_SMEM>>>(
        pB, 10, lins_b + 1 * HH, pB, pA, nN, nullptr, nullptr, nullptr);
    gemm_p<false, true, true, true, 1><<<PG, 256, GEMM_SMEM>>>(
        pA, 11, lins_b + 2 * HH, pA, pB, nN, batch, nullptr, nullptr);

    const int n32b = (NN * 32 + 255) / 256;
    norm_center<<<n32b, 256>>>(pB, batch, norm_ms, pC);

    gemm_p<false, true, false, false, 2><<<PG, 256, GEMM_SMEM>>>(
        pC, 12, final_b, nullptr, (float*)d_out, nN, batch, norm_w, norm_b);
}

// round 16
// speedup vs baseline: 1.2962x; 1.2962x over previous
#include <cuda_runtime.h>
#include <cuda_bf16.h>
#include <cuda_fp16.h>

#define NN 50000
#define EE 1000000
#define BB 512
#define HH 128
#define MID 64
#define IN1 54
#define IN2 18

typedef unsigned long long u64;
typedef unsigned int u32;

#define FMA2(d, a, b, c) asm("fma.rn.f32x2 %0, %1, %2, %3;" : "=l"(d) : "l"(a), "l"(b), "l"(c))

__device__ __forceinline__ u64 pack2(float lo, float hi) {
    u64 r; asm("mov.b64 %0, {%1, %2};" : "=l"(r) : "f"(lo), "f"(hi)); return r;
}
__device__ __forceinline__ void unpack2(u64 v, float& lo, float& hi) {
    asm("mov.b64 {%0, %1}, %2;" : "=f"(lo), "=f"(hi) : "l"(v));
}
__device__ __forceinline__ void red_add_v4(float* addr, float4 v) {
    asm volatile("red.global.add.v4.f32 [%0], {%1, %2, %3, %4};"
                 :: "l"(addr), "f"(v.x), "f"(v.y), "f"(v.z), "f"(v.w) : "memory");
}
__device__ __forceinline__ void red_add_v2(float* addr, float a, float b) {
    asm volatile("red.global.add.v2.f32 [%0], {%1, %2};"
                 :: "l"(addr), "f"(a), "f"(b) : "memory");
}
__device__ __forceinline__ void red_add_f(float* addr, float v) {
    asm volatile("red.global.add.f32 [%0], %1;" :: "l"(addr), "f"(v) : "memory");
}
// bf16 mma (node chain)
#define MMA16816(c0, c1, c2, c3, a0, a1, a2, a3, b0, b1) \
    asm volatile("mma.sync.aligned.m16n8k16.row.col.f32.bf16.bf16.f32 " \
                 "{%0,%1,%2,%3}, {%4,%5,%6,%7}, {%8,%9}, {%0,%1,%2,%3};" \
                 : "+f"(c0), "+f"(c1), "+f"(c2), "+f"(c3) \
                 : "r"(a0), "r"(a1), "r"(a2), "r"(a3), "r"(b0), "r"(b1))
// fp16 mma (edge path)
#define MMAH16816(c0, c1, c2, c3, a0, a1, a2, a3, b0, b1) \
    asm volatile("mma.sync.aligned.m16n8k16.row.col.f32.f16.f16.f32 " \
                 "{%0,%1,%2,%3}, {%4,%5,%6,%7}, {%8,%9}, {%0,%1,%2,%3};" \
                 : "+f"(c0), "+f"(c1), "+f"(c2), "+f"(c3) \
                 : "r"(a0), "r"(a1), "r"(a2), "r"(a3), "r"(b0), "r"(b1))

__device__ __forceinline__ u32 pack_bf2(float e0, float e1) {
    __nv_bfloat162 h = __floats2bfloat162_rn(e0, e1);
    return *(u32*)&h;
}
__device__ __forceinline__ u32 pack_h2(float e0, float e1) {
    __half2 h = __floats2half2_rn(e0, e1);
    return *(u32*)&h;
}

// ---------------- scratch ----------------
__device__ float g_xact[NN * HH];
__device__ float g_agg1[NN * HH];
__device__ float g_agg2[NN * HH];
__device__ float g_A[NN * HH];
__device__ float g_B[NN * HH];
__device__ float g_C[NN * HH];
__device__ float g_mean[BB * HH];
__device__ float g_var[BB * HH];
__device__ float g_cnt[BB];
__device__ __half g_m1h[EE * MID];   // single fp16 per element
__device__ __half g_m2h[EE * MID];
// preconverted node-GEMM weights: 13 matrices of 128x128, bf16 hi/lo planes (flat [c][k])
__device__ __nv_bfloat16 g_Wh[13 * 128 * 128];
__device__ __nv_bfloat16 g_Wl[13 * 128 * 128];

__global__ void zero_kernel() {
    int idx = blockIdx.x * blockDim.x + threadIdx.x;
    if (idx < NN * HH) { g_agg1[idx] = 0.f; g_agg2[idx] = 0.f; }
    if (idx < BB * HH) { g_mean[idx] = 0.f; g_var[idx] = 0.f; }
    if (idx < BB) g_cnt[idx] = 0.f;
}

// ---------------- weight prep: fp32 -> bf16 hi/lo planes ----------------
struct WSrc { const float* p; int ldw; };
struct WPack { WSrc w[13]; };

__global__ void prep_weights(WPack wp) {
    int idx = blockIdx.x * blockDim.x + threadIdx.x;
    if (idx >= 13 * 16384) return;
    int m = idx >> 14, r = idx & 16383, c = r >> 7, k = r & 127;
    float v = wp.w[m].p[(size_t)c * wp.w[m].ldw + k];
    __nv_bfloat16 h = __float2bfloat16_rn(v);
    g_Wh[idx] = h;
    g_Wl[idx] = __float2bfloat16_rn(v - __bfloat162float(h));
}

// ---------------- persistent node GEMM via split-bf16 HMMA ----------------
constexpr int GP = 136;
constexpr int GEMM_SMEM = (64 + 64 + 128 + 128) * GP * 2;

template <bool ACCUM, bool EPI, bool SWISH, bool RESID, int FUSE>
__global__ __launch_bounds__(256, 2) void gemm_p(
    const float* __restrict__ A, int widx,
    const float* __restrict__ bias, const float* __restrict__ resid,
    float* __restrict__ out, int nrows,
    const int* __restrict__ batch, const float* __restrict__ nw, const float* __restrict__ nb)
{
    extern __shared__ char smc[];
    __nv_bfloat16* Ahi = (__nv_bfloat16*)(smc);
    __nv_bfloat16* Alo = (__nv_bfloat16*)(smc + 64 * GP * 2);
    __nv_bfloat16* Whi = (__nv_bfloat16*)(smc + 128 * GP * 2);
    __nv_bfloat16* Wlo = (__nv_bfloat16*)(smc + 256 * GP * 2);

    const int tid  = threadIdx.x;
    const int warp = tid >> 5;
    const int lane = tid & 31;
    const int fg   = lane >> 2;
    const int ft   = lane & 3;
    const int rg   = warp & 3;
    const int chf  = warp >> 2;

    {
        const u32* srcH = (const u32*)(g_Wh + (size_t)widx * 16384);
        const u32* srcL = (const u32*)(g_Wl + (size_t)widx * 16384);
        for (int i = tid; i < 128 * 64; i += 256) {
            int c = i >> 6, kp = i & 63;
            ((u32*)Whi)[c * 68 + kp] = srcH[i];
            ((u32*)Wlo)[c * 68 + kp] = srcL[i];
        }
    }

    const int ntiles = (nrows + 63) >> 6;

    float4 pre[8];
    auto ldA = [&](int tt) {
#pragma unroll
        for (int j = 0; j < 8; j++) {
            int idx = tid + 256 * j;
            int r = idx >> 5, kp4 = idx & 31;
            int gr = (tt << 6) + r;
            float4 v = (gr < nrows) ? *(const float4*)(A + (size_t)gr * 128 + 4 * kp4)
                                    : make_float4(0.f, 0.f, 0.f, 0.f);
            if (FUSE == 2) {
                if (gr < nrows) {
                    int b = __ldg(batch + gr);
                    float rcnt = 1.f / fmaxf(g_cnt[b], 1.f);
                    float4 vv = *(const float4*)(&g_var[b * HH + 4 * kp4]);
                    float4 w4 = *(const float4*)(nw + 4 * kp4);
                    float4 b4 = *(const float4*)(nb + 4 * kp4);
                    v.x = w4.x * v.x * rsqrtf(vv.x * rcnt + 1e-5f) + b4.x;
                    v.y = w4.y * v.y * rsqrtf(vv.y * rcnt + 1e-5f) + b4.y;
                    v.z = w4.z * v.z * rsqrtf(vv.z * rcnt + 1e-5f) + b4.z;
                    v.w = w4.w * v.w * rsqrtf(vv.w * rcnt + 1e-5f) + b4.w;
                }
            }
            pre[j] = v;
        }
    };

    int t = blockIdx.x;
    if (t < ntiles) ldA(t);

    for (; t < ntiles; t += gridDim.x) {
        const int r0 = t << 6;
        __syncthreads();

#pragma unroll
        for (int j = 0; j < 8; j++) {
            int idx = tid + 256 * j;
            int r = idx >> 5, kp4 = idx & 31;
            float4 v = pre[j];
            __nv_bfloat162 h01 = __floats2bfloat162_rn(v.x, v.y);
            __nv_bfloat162 h23 = __floats2bfloat162_rn(v.z, v.w);
            __nv_bfloat162 l01 = __floats2bfloat162_rn(v.x - __bfloat162float(h01.x),
                                                       v.y - __bfloat162float(h01.y));
            __nv_bfloat162 l23 = __floats2bfloat162_rn(v.z - __bfloat162float(h23.x),
                                                       v.w - __bfloat162float(h23.y));
            ((u64*)(Ahi + r * GP))[kp4] = (u64)(*(u32*)&h01) | ((u64)(*(u32*)&h23) << 32);
            ((u64*)(Alo + r * GP))[kp4] = (u64)(*(u32*)&l01) | ((u64)(*(u32*)&l23) << 32);
        }
        __syncthreads();

        const int tn = t + gridDim.x;
        if (tn < ntiles) ldA(tn);

        float acc[8][4];
#pragma unroll
        for (int nt = 0; nt < 8; nt++)
#pragma unroll
            for (int q = 0; q < 4; q++) acc[nt][q] = 0.f;

        const int m0 = rg * 16 + fg;
#pragma unroll
        for (int kstep = 0; kstep < 8; kstep++) {
            const int k0 = kstep * 16 + 2 * ft;
            u32 ah0 = *(const u32*)(Ahi + m0 * GP + k0);
            u32 ah1 = *(const u32*)(Ahi + (m0 + 8) * GP + k0);
            u32 ah2 = *(const u32*)(Ahi + m0 * GP + k0 + 8);
            u32 ah3 = *(const u32*)(Ahi + (m0 + 8) * GP + k0 + 8);
            u32 al0 = *(const u32*)(Alo + m0 * GP + k0);
            u32 al1 = *(const u32*)(Alo + (m0 + 8) * GP + k0);
            u32 al2 = *(const u32*)(Alo + m0 * GP + k0 + 8);
            u32 al3 = *(const u32*)(Alo + (m0 + 8) * GP + k0 + 8);
#pragma unroll
            for (int nt = 0; nt < 8; nt++) {
                const int c = chf * 64 + nt * 8 + fg;
                u32 bh0 = *(const u32*)(Whi + c * GP + k0);
                u32 bh1 = *(const u32*)(Whi + c * GP + k0 + 8);
                u32 bl0 = *(const u32*)(Wlo + c * GP + k0);
                u32 bl1 = *(const u32*)(Wlo + c * GP + k0 + 8);
                MMA16816(acc[nt][0], acc[nt][1], acc[nt][2], acc[nt][3],
                         ah0, ah1, ah2, ah3, bh0, bh1);
                MMA16816(acc[nt][0], acc[nt][1], acc[nt][2], acc[nt][3],
                         al0, al1, al2, al3, bh0, bh1);
                MMA16816(acc[nt][0], acc[nt][1], acc[nt][2], acc[nt][3],
                         ah0, ah1, ah2, ah3, bl0, bl1);
            }
        }

        const int rA = r0 + m0, rBr = r0 + m0 + 8;
        int bA = 0, bB = 0;
        if (FUSE == 1) {
            if (rA < nrows)  bA = __ldg(batch + rA);
            if (rBr < nrows) bB = __ldg(batch + rBr);
        }
#pragma unroll
        for (int nt = 0; nt < 8; nt++) {
            const int c = chf * 64 + nt * 8 + 2 * ft;
            float v0 = acc[nt][0], v1 = acc[nt][1];
            float v2 = acc[nt][2], v3 = acc[nt][3];
            if (EPI) {
                float2 bv = *(const float2*)(bias + c);
                v0 += bv.x; v1 += bv.y; v2 += bv.x; v3 += bv.y;
            }
            if (rA < nrows) {
                float* orow = out + (size_t)rA * 128 + c;
                if (ACCUM) { float2 pv = *(const float2*)orow; v0 += pv.x; v1 += pv.y; }
                if (SWISH) {
                    v0 = v0 / (1.f + __expf(-v0));
                    v1 = v1 / (1.f + __expf(-v1));
                }
                if (RESID) {
                    float2 rv = *(const float2*)(resid + (size_t)rA * 128 + c);
                    v0 += rv.x; v1 += rv.y;
                }
                *(float2*)orow = make_float2(v0, v1);
                if (FUSE == 1) red_add_v2(&g_mean[bA * HH + c], v0, v1);
            }
            if (rBr < nrows) {
                float* orow = out + (size_t)rBr * 128 + c;
                if (ACCUM) { float2 pv = *(const float2*)orow; v2 += pv.x; v3 += pv.y; }
                if (SWISH) {
                    v2 = v2 / (1.f + __expf(-v2));
                    v3 = v3 / (1.f + __expf(-v3));
                }
                if (RESID) {
                    float2 rv = *(const float2*)(resid + (size_t)rBr * 128 + c);
                    v2 += rv.x; v3 += rv.y;
                }
                *(float2*)orow = make_float2(v2, v3);
                if (FUSE == 1) red_add_v2(&g_mean[bB * HH + c], v2, v3);
            }
        }
        if (FUSE == 1 && chf == 0 && ft == 0) {
            if (rA < nrows)  red_add_f(&g_cnt[bA], 1.f);
            if (rBr < nrows) red_add_f(&g_cnt[bB], 1.f);
        }
    }
}

// ---------------- edge stage 1: EB=32 tiles, m stored as single fp16 ----------------
constexpr int EBM = 32;

__global__ __launch_bounds__(256) void edge_mlp1(
    const float* __restrict__ feat1, const float* __restrict__ feat2,
    const float* __restrict__ W1a, const float* __restrict__ W1b, int nE)
{
    __shared__ __align__(16) float f1s[EBM * IN1];
    __shared__ __align__(16) float f2s[EBM * IN2];
    __shared__ __align__(16) float Ws1a[MID * IN1];
    __shared__ __align__(16) float Ws1b[MID * IN2];

    const int tid = threadIdx.x;
    for (int i = tid; i < MID * IN1; i += 256) Ws1a[i] = W1a[i];
    for (int i = tid; i < MID * IN2; i += 256) Ws1b[i] = W1b[i];
    __syncthreads();

    const int ntiles = nE / EBM;
    const int k = tid & 63, g = tid >> 6;

    for (int t = blockIdx.x; t < ntiles; t += gridDim.x) {
        const int e0 = t * EBM;
        for (int i = tid; i < EBM * IN1; i += 256) f1s[i] = feat1[(size_t)e0 * IN1 + i];
        for (int i = tid; i < EBM * IN2; i += 256) f2s[i] = feat2[(size_t)e0 * IN2 + i];
        __syncthreads();

        {
            const u64* wrow = (const u64*)(Ws1a + k * IN1);
            u64 a[8];
#pragma unroll
            for (int q = 0; q < 8; q++) a[q] = 0ull;
#pragma unroll
            for (int jp = 0; jp < IN1 / 2; jp++) {
                u64 w = wrow[jp];
#pragma unroll
                for (int q = 0; q < 8; q++) {
                    const u64* fr = (const u64*)(f1s + (g + 4 * q) * IN1);
                    FMA2(a[q], fr[jp], w, a[q]);
                }
            }
            float lo, hi;
#pragma unroll
            for (int q = 0; q < 8; q++) {
                unpack2(a[q], lo, hi);
                g_m1h[(size_t)(e0 + g + 4 * q) * MID + k] = __float2half_rn(lo + hi);
            }
        }
        {
            const u64* wrow = (const u64*)(Ws1b + k * IN2);
            u64 a[8];
#pragma unroll
            for (int q = 0; q < 8; q++) a[q] = 0ull;
#pragma unroll
            for (int jp = 0; jp < IN2 / 2; jp++) {
                u64 w = wrow[jp];
#pragma unroll
                for (int q = 0; q < 8; q++) {
                    const u64* fr = (const u64*)(f2s + (g + 4 * q) * IN2);
                    FMA2(a[q], fr[jp], w, a[q]);
                }
            }
            float lo, hi;
#pragma unroll
            for (int q = 0; q < 8; q++) {
                unpack2(a[q], lo, hi);
                g_m2h[(size_t)(e0 + g + 4 * q) * MID + k] = __float2half_rn(lo + hi);
            }
        }
        __syncthreads();
    }
}

// ---------------- edge stage 2: fp16 1-term HMMA (unchanged from R14) ----------------
constexpr int XP = 132;
constexpr int EB2 = 32;

__global__ __launch_bounds__(256, 3) void edge_scatter(
    const int* __restrict__ ei,
    const float* __restrict__ W2a, const float* __restrict__ W2b,
    const float* __restrict__ xact,
    float* __restrict__ agg1, float* __restrict__ agg2, int nE)
{
    __shared__ __align__(16) float xs[2][EB2 * XP];

    const int tid  = threadIdx.x;
    const int warp = tid >> 5;
    const int lane = tid & 31;
    const int fg   = lane >> 2;
    const int ft   = lane & 3;

    u32 bhf[4][4][2];
    {
        const float* W2 = (warp < 4) ? W2a : W2b;
        const int nbase = (warp & 3) * 32;
#pragma unroll
        for (int nt = 0; nt < 4; nt++) {
            const float* wrow = W2 + (size_t)(nbase + nt * 8 + fg) * MID;
#pragma unroll
            for (int kt = 0; kt < 4; kt++) {
#pragma unroll
                for (int half = 0; half < 2; half++) {
                    int k0 = kt * 16 + half * 8 + 2 * ft;
                    bhf[nt][kt][half] = pack_h2(wrow[k0], wrow[k0 + 1]);
                }
            }
        }
    }

    const int ntiles = nE / EB2;

    auto do_gather = [&](int buf, int tt) {
        const int e0n = tt * EB2;
#pragma unroll
        for (int j = 0; j < 4; j++) {
            int idx = tid + 256 * j;
            int e = idx >> 5, h4 = (idx & 31) << 2;
            int src = __ldg(ei + e0n + e);
            float4 v = *(const float4*)(xact + (size_t)src * HH + h4);
            *(float4*)(&xs[buf][e * XP + h4]) = v;
        }
    };

    int t = blockIdx.x;
    if (t < ntiles) do_gather(0, t);

    int it = 0;
    for (; t < ntiles; t += gridDim.x, it ^= 1) {
        const int cur = it, nxt = it ^ 1;
        const int tn = t + gridDim.x;
        __syncthreads();
        if (tn < ntiles) do_gather(nxt, tn);

        const __half* mpl = (warp < 4) ? g_m1h : g_m2h;
        float* agg = (warp < 4) ? agg1 : agg2;
        const int nbase = (warp & 3) * 32;

#pragma unroll
        for (int sb = 0; sb < 2; sb++) {
            const int e0 = t * EB2 + sb * 16;
            const int exs = sb * 16;

            float acc[4][4];
#pragma unroll
            for (int nt = 0; nt < 4; nt++)
#pragma unroll
                for (int q = 0; q < 4; q++) acc[nt][q] = 0.f;

            const u32* rowA = (const u32*)(mpl + (size_t)(e0 + fg) * MID);
            const u32* rowB = (const u32*)(mpl + (size_t)(e0 + fg + 8) * MID);
#pragma unroll
            for (int kt = 0; kt < 4; kt++) {
                u32 a0 = rowA[kt * 8 + ft];
                u32 a1 = rowB[kt * 8 + ft];
                u32 a2 = rowA[kt * 8 + ft + 4];
                u32 a3 = rowB[kt * 8 + ft + 4];
#pragma unroll
                for (int nt = 0; nt < 4; nt++) {
                    MMAH16816(acc[nt][0], acc[nt][1], acc[nt][2], acc[nt][3],
                              a0, a1, a2, a3, bhf[nt][kt][0], bhf[nt][kt][1]);
                }
            }

            const int dA = __ldg(ei + nE + e0 + fg);
            const int dB = __ldg(ei + nE + e0 + fg + 8);
#pragma unroll
            for (int nt = 0; nt < 4; nt++) {
                int ch = nbase + nt * 8 + 2 * ft;
                float2 xga = *(const float2*)(&xs[cur][(exs + fg) * XP + ch]);
                float2 xgb = *(const float2*)(&xs[cur][(exs + fg + 8) * XP + ch]);
                red_add_v2(agg + (size_t)dA * HH + ch, acc[nt][0] * xga.x, acc[nt][1] * xga.y);
                red_add_v2(agg + (size_t)dB * HH + ch, acc[nt][2] * xgb.x, acc[nt][3] * xgb.y);
            }
        }
    }
}

// ---------------- GraphNorm center ----------------
__global__ void norm_center(const float* __restrict__ hin, const int* __restrict__ batch,
                            const float* __restrict__ ms, float* __restrict__ hc_out) {
    int idx = blockIdx.x * blockDim.x + threadIdx.x;
    if (idx >= NN * 32) return;
    int n = idx >> 5, c4 = (idx & 31) << 2;
    int b = batch[n];
    float rcnt = 1.f / fmaxf(g_cnt[b], 1.f);
    float4 hv = *(const float4*)(hin + (size_t)n * HH + c4);
    float4 mv = *(const float4*)(&g_mean[b * HH + c4]);
    float4 msv = *(const float4*)(ms + c4);
    float4 hc;
    hc.x = hv.x - mv.x * rcnt * msv.x;
    hc.y = hv.y - mv.y * rcnt * msv.y;
    hc.z = hv.z - mv.z * rcnt * msv.z;
    hc.w = hv.w - mv.w * rcnt * msv.w;
    *(float4*)(hc_out + (size_t)n * HH + c4) = hc;
    float4 sq = make_float4(hc.x * hc.x, hc.y * hc.y, hc.z * hc.z, hc.w * hc.w);
    red_add_v4(&g_var[b * HH + c4], sq);
}

// ---------------- launch (sequential, R14 structure) ----------------
extern "C" void kernel_launch(void* const* d_in, const int* in_sizes, int n_in,
                              void* d_out, int out_size)
{
    const float* x        = (const float*)d_in[0];
    const float* feature1 = (const float*)d_in[1];
    const float* feature2 = (const float*)d_in[2];
    const int*   ei       = (const int*)d_in[3];
    const int*   batch    = (const int*)d_in[4];
    const float* lin_W    = (const float*)d_in[5];
    const float* lin_b    = (const float*)d_in[6];
    const float* f1_W1    = (const float*)d_in[7];
    const float* f1_W2    = (const float*)d_in[8];
    const float* f2_W1    = (const float*)d_in[9];
    const float* f2_W2    = (const float*)d_in[10];
    const float* c1_rel_W = (const float*)d_in[11];
    const float* c1_rel_b = (const float*)d_in[12];
    const float* c1_rt_W  = (const float*)d_in[13];
    const float* c2_rel_W = (const float*)d_in[14];
    const float* c2_rel_b = (const float*)d_in[15];
    const float* c2_rt_W  = (const float*)d_in[16];
    const float* lin1_W   = (const float*)d_in[17];
    const float* lin1_b   = (const float*)d_in[18];
    const float* lin2_W   = (const float*)d_in[19];
    const float* lin2_b   = (const float*)d_in[20];
    const float* cat_W    = (const float*)d_in[21];
    const float* cat_b    = (const float*)d_in[22];
    const float* norm_w   = (const float*)d_in[23];
    const float* norm_b   = (const float*)d_in[24];
    const float* norm_ms  = (const float*)d_in[25];
    const float* lins_W   = (const float*)d_in[26];
    const float* lins_b   = (const float*)d_in[27];
    const float* final_W  = (const float*)d_in[28];
    const float* final_b  = (const float*)d_in[29];

    const int nN = in_sizes[0] / HH;
    const int nE = in_sizes[3] / 2;

    float *pxact, *pagg1, *pagg2, *pA, *pB, *pC;
    cudaGetSymbolAddress((void**)&pxact, g_xact);
    cudaGetSymbolAddress((void**)&pagg1, g_agg1);
    cudaGetSymbolAddress((void**)&pagg2, g_agg2);
    cudaGetSymbolAddress((void**)&pA, g_A);
    cudaGetSymbolAddress((void**)&pB, g_B);
    cudaGetSymbolAddress((void**)&pC, g_C);

    cudaFuncSetAttribute(gemm_p<false, true,  true,  false, 0>, cudaFuncAttributeMaxDynamicSharedMemorySize, GEMM_SMEM);
    cudaFuncSetAttribute(gemm_p<false, false, false, false, 0>, cudaFuncAttributeMaxDynamicSharedMemorySize, GEMM_SMEM);
    cudaFuncSetAttribute(gemm_p<true,  true,  false, false, 0>, cudaFuncAttributeMaxDynamicSharedMemorySize, GEMM_SMEM);
    cudaFuncSetAttribute(gemm_p<true,  true,  false, true,  0>, cudaFuncAttributeMaxDynamicSharedMemorySize, GEMM_SMEM);
    cudaFuncSetAttribute(gemm_p<false, true,  true,  true,  0>, cudaFuncAttributeMaxDynamicSharedMemorySize, GEMM_SMEM);
    cudaFuncSetAttribute(gemm_p<false, true,  true,  true,  1>, cudaFuncAttributeMaxDynamicSharedMemorySize, GEMM_SMEM);
    cudaFuncSetAttribute(gemm_p<false, true,  false, false, 2>, cudaFuncAttributeMaxDynamicSharedMemorySize, GEMM_SMEM);

    const int PG = 296;

    WPack wp;
    wp.w[0]  = { lin_W, HH };
    wp.w[1]  = { c1_rel_W, HH };
    wp.w[2]  = { c1_rt_W, HH };
    wp.w[3]  = { lin1_W, HH };
    wp.w[4]  = { c2_rel_W, HH };
    wp.w[5]  = { c2_rt_W, HH };
    wp.w[6]  = { lin2_W, HH };
    wp.w[7]  = { cat_W, 2 * HH };
    wp.w[8]  = { cat_W + HH, 2 * HH };
    wp.w[9]  = { lins_W + 0 * HH * HH, HH };
    wp.w[10] = { lins_W + 1 * HH * HH, HH };
    wp.w[11] = { lins_W + 2 * HH * HH, HH };
    wp.w[12] = { final_W, HH };

    zero_kernel<<<(NN * HH + 255) / 256, 256>>>();
    prep_weights<<<(13 * 16384 + 255) / 256, 256>>>(wp);

    edge_mlp1<<<592, 256>>>(feature1, feature2, f1_W1, f2_W1, nE);

    gemm_p<false, true, true, false, 0><<<PG, 256, GEMM_SMEM>>>(
        x, 0, lin_b, nullptr, pxact, nN, nullptr, nullptr, nullptr);

    edge_scatter<<<444, 256>>>(ei, f1_W2, f2_W2, pxact, pagg1, pagg2, nE);

    gemm_p<false, false, false, false, 0><<<PG, 256, GEMM_SMEM>>>(
        pagg1, 1, nullptr, nullptr, pA, nN, nullptr, nullptr, nullptr);
    gemm_p<true, true, false, false, 0><<<PG, 256, GEMM_SMEM>>>(
        pxact, 2, c1_rel_b, nullptr, pA, nN, nullptr, nullptr, nullptr);
    gemm_p<false, true, true, false, 0><<<PG, 256, GEMM_SMEM>>>(
        pA, 3, lin1_b, nullptr, pB, nN, nullptr, nullptr, nullptr);
    gemm_p<false, false, false, false, 0><<<PG, 256, GEMM_SMEM>>>(
        pagg2, 4, nullptr, nullptr, pA, nN, nullptr, nullptr, nullptr);
    gemm_p<true, true, false, false, 0><<<PG, 256, GEMM_SMEM>>>(
        pxact, 5, c2_rel_b, nullptr, pA, nN, nullptr, nullptr, nullptr);
    gemm_p<false, true, true, false, 0><<<PG, 256, GEMM_SMEM>>>(
        pA, 6, lin2_b, nullptr, pC, nN, nullptr, nullptr, nullptr);
    gemm_p<false, false, false, false, 0><<<PG, 256, GEMM_SMEM>>>(
        pB, 7, nullptr, nullptr, pA, nN, nullptr, nullptr, nullptr);
    gemm_p<true, true, false, true, 0><<<PG, 256, GEMM_SMEM>>>(
        pC, 8, cat_b, pxact, pA, nN, nullptr, nullptr, nullptr);
    gemm_p<false, true, true, true, 0><<<PG, 256, GEMM_SMEM>>>(
        pA, 9,  lins_b + 0 * HH, pA, pB, nN, nullptr, nullptr, nullptr);
    gemm_p<false, true, true, true, 0><<<PG, 256, GEMM_SMEM>>>(
        pB, 10, lins_b + 1 * HH, pB, pA, nN, nullptr, nullptr, nullptr);
    gemm_p<false, true, true, true, 1><<<PG, 256, GEMM_SMEM>>>(
        pA, 11, lins_b + 2 * HH, pA, pB, nN, batch, nullptr, nullptr);

    const int n32b = (NN * 32 + 255) / 256;
    norm_center<<<n32b, 256>>>(pB, batch, norm_ms, pC);

    gemm_p<false, true, false, false, 2><<<PG, 256, GEMM_SMEM>>>(
        pC, 12, final_b, nullptr, (float*)d_out, nN, batch, norm_w, norm_b);
}